// round 3
// baseline (speedup 1.0000x reference)
#include <cuda_runtime.h>
#include <cuda_bf16.h>
#include <math.h>

// Problem dims (fixed)
#define BI   256          // I
#define BJ   256          // J
#define CC   128          // C
#define HH   4            // heads
#define CH   32           // per-head dim
#define MROWS (BI*BJ)     // 65536

// ---------------- scratch (device globals; no allocation) ----------------
__device__ float g_xn[(size_t)MROWS * CC];
__device__ float g_q [(size_t)MROWS * CC];
__device__ float g_k [(size_t)MROWS * CC];
__device__ float g_v [(size_t)MROWS * CC];
__device__ float g_g [(size_t)MROWS * CC];
__device__ float g_tri[(size_t)HH * BI * BJ];
__device__ float g_o [(size_t)MROWS * CC];

// ---------------- LayerNorm: one block (128 thr) per row ----------------
__global__ void ln_kernel(const float* __restrict__ x,
                          const float* __restrict__ w,
                          const float* __restrict__ b) {
    int row = blockIdx.x;
    int t = threadIdx.x;
    float v = x[(size_t)row * CC + t];
    float s = v, sq = v * v;
    #pragma unroll
    for (int off = 16; off; off >>= 1) {
        s  += __shfl_xor_sync(0xffffffffu, s,  off);
        sq += __shfl_xor_sync(0xffffffffu, sq, off);
    }
    __shared__ float sh[8];
    int wid = t >> 5, lane = t & 31;
    if (lane == 0) { sh[wid] = s; sh[4 + wid] = sq; }
    __syncthreads();
    s  = sh[0] + sh[1] + sh[2] + sh[3];
    sq = sh[4] + sh[5] + sh[6] + sh[7];
    float mu  = s * (1.0f / CC);
    float var = sq * (1.0f / CC) - mu * mu;
    float rs  = rsqrtf(var + 1e-5f);
    g_xn[(size_t)row * CC + t] = (v - mu) * rs * w[t] + b[t];
}

// ---------------- tri bias: tri[h][i][j] = xn[i,j,:] . w_tri[:,h] --------
__global__ void tri_kernel(const float* __restrict__ w_tri) {
    int row  = blockIdx.x * 8 + (threadIdx.x >> 5);   // 0..65535
    int lane = threadIdx.x & 31;
    float a0 = 0.f, a1 = 0.f, a2 = 0.f, a3 = 0.f;
    #pragma unroll
    for (int c0 = 0; c0 < CC; c0 += 32) {
        float xv = g_xn[(size_t)row * CC + c0 + lane];
        float4 w = *(const float4*)(w_tri + (size_t)(c0 + lane) * 4);
        a0 += xv * w.x; a1 += xv * w.y; a2 += xv * w.z; a3 += xv * w.w;
    }
    #pragma unroll
    for (int off = 16; off; off >>= 1) {
        a0 += __shfl_xor_sync(0xffffffffu, a0, off);
        a1 += __shfl_xor_sync(0xffffffffu, a1, off);
        a2 += __shfl_xor_sync(0xffffffffu, a2, off);
        a3 += __shfl_xor_sync(0xffffffffu, a3, off);
    }
    if (lane == 0) {
        g_tri[0 * (size_t)MROWS + row] = a0;
        g_tri[1 * (size_t)MROWS + row] = a1;
        g_tri[2 * (size_t)MROWS + row] = a2;
        g_tri[3 * (size_t)MROWS + row] = a3;
    }
}

// ---------------- SGEMM: C[M,128] = alpha * A[M,128] @ B[128,128] + bias --
// 128x128 block tile, 8x8 per thread, 256 threads.
__global__ void __launch_bounds__(256)
gemm_nn_k128(const float* __restrict__ A, const float* __restrict__ B,
             float* __restrict__ C, float alpha, const float* __restrict__ bias) {
    __shared__ float As[16][132];   // transposed A tile: As[k][m], padded
    __shared__ float Bs[16][128];
    int tid = threadIdx.x;
    int m0  = blockIdx.x * 128;
    int ty  = tid >> 4, tx = tid & 15;   // 16x16 thread grid
    float acc[8][8];
    #pragma unroll
    for (int a = 0; a < 8; a++)
        #pragma unroll
        for (int b = 0; b < 8; b++) acc[a][b] = 0.f;

    for (int k0 = 0; k0 < 128; k0 += 16) {
        // A tile: 128 rows x 16 k = 512 float4
        #pragma unroll
        for (int l = 0; l < 2; l++) {
            int idx = tid + l * 256;
            int ar = idx >> 2;          // 0..127
            int ac = (idx & 3) * 4;     // 0,4,8,12
            float4 f = *(const float4*)(A + (size_t)(m0 + ar) * 128 + k0 + ac);
            As[ac + 0][ar] = f.x;
            As[ac + 1][ar] = f.y;
            As[ac + 2][ar] = f.z;
            As[ac + 3][ar] = f.w;
        }
        // B tile: 16 rows x 128 = 512 float4
        #pragma unroll
        for (int l = 0; l < 2; l++) {
            int idx = tid + l * 256;
            int br = idx >> 5;          // 0..15
            int bc = (idx & 31) * 4;    // 0..124
            *(float4*)(&Bs[br][bc]) = *(const float4*)(B + (size_t)(k0 + br) * 128 + bc);
        }
        __syncthreads();
        #pragma unroll
        for (int kk = 0; kk < 16; kk++) {
            float ra[8], rb[8];
            *(float4*)(ra)     = *(float4*)(&As[kk][ty * 8]);
            *(float4*)(ra + 4) = *(float4*)(&As[kk][ty * 8 + 4]);
            *(float4*)(rb)     = *(float4*)(&Bs[kk][tx * 8]);
            *(float4*)(rb + 4) = *(float4*)(&Bs[kk][tx * 8 + 4]);
            #pragma unroll
            for (int a = 0; a < 8; a++)
                #pragma unroll
                for (int b = 0; b < 8; b++)
                    acc[a][b] += ra[a] * rb[b];
        }
        __syncthreads();
    }
    #pragma unroll
    for (int a = 0; a < 8; a++) {
        int m = m0 + ty * 8 + a;
        #pragma unroll
        for (int b = 0; b < 8; b += 4) {
            int n = tx * 8 + b;
            float4 o;
            o.x = alpha * acc[a][b + 0] + (bias ? bias[n + 0] : 0.f);
            o.y = alpha * acc[a][b + 1] + (bias ? bias[n + 1] : 0.f);
            o.z = alpha * acc[a][b + 2] + (bias ? bias[n + 2] : 0.f);
            o.w = alpha * acc[a][b + 3] + (bias ? bias[n + 3] : 0.f);
            *(float4*)(C + (size_t)m * 128 + n) = o;
        }
    }
}

// ---------------- attention: block per (qtile=64, h, i) ------------------
// smem: q_s[32][68] (d-major), k_s[32][260] (d-major), v_s[256][32],
//       s_s[64][260], mb_s[256]
#define QS_STR 68
#define KS_STR 260
#define SS_STR 260
#define SM_Q   0
#define SM_K   (SM_Q + 32 * QS_STR)
#define SM_V   (SM_K + 32 * KS_STR)
#define SM_S   (SM_V + 256 * 32)
#define SM_MB  (SM_S + 64 * SS_STR)
#define ATTN_SMEM_FLOATS (SM_MB + 256)

__global__ void __launch_bounds__(256)
attn_kernel(const float* __restrict__ mask) {
    extern __shared__ float sm[];
    float* q_s  = sm + SM_Q;
    float* k_s  = sm + SM_K;
    float* v_s  = sm + SM_V;
    float* s_s  = sm + SM_S;
    float* mb_s = sm + SM_MB;

    int tid = threadIdx.x;
    int qt = blockIdx.x;       // 0..3 (q tile of 64)
    int h  = blockIdx.y;       // 0..3
    int i  = blockIdx.z;       // 0..255

    mb_s[tid] = 1.0e9f * (mask[(size_t)i * BJ + tid] - 1.0f);

    // q tile (transposed to d-major)
    #pragma unroll
    for (int l = 0; l < 2; l++) {
        int idx = tid + l * 256;
        int jr = idx >> 3;                 // 0..63
        int d4 = (idx & 7) * 4;
        int jg = qt * 64 + jr;
        float4 f = *(const float4*)(g_q + (((size_t)(i * BJ + jg) * HH + h) * CH) + d4);
        q_s[(d4 + 0) * QS_STR + jr] = f.x;
        q_s[(d4 + 1) * QS_STR + jr] = f.y;
        q_s[(d4 + 2) * QS_STR + jr] = f.z;
        q_s[(d4 + 3) * QS_STR + jr] = f.w;
    }
    // k (transposed), v (natural)
    #pragma unroll
    for (int l = 0; l < 8; l++) {
        int idx = tid + l * 256;
        int jr = idx >> 3;                 // 0..255
        int d4 = (idx & 7) * 4;
        size_t base = ((size_t)(i * BJ + jr) * HH + h) * CH + d4;
        float4 fk = *(const float4*)(g_k + base);
        k_s[(d4 + 0) * KS_STR + jr] = fk.x;
        k_s[(d4 + 1) * KS_STR + jr] = fk.y;
        k_s[(d4 + 2) * KS_STR + jr] = fk.z;
        k_s[(d4 + 3) * KS_STR + jr] = fk.w;
        *(float4*)(&v_s[jr * 32 + d4]) = *(const float4*)(g_v + base);
    }
    __syncthreads();

    // scores: 8q x 8k per thread (q-group uniform per warp -> broadcast LDS)
    {
        int qg = tid >> 5;         // 0..7
        int kg = tid & 31;         // 0..31
        int q0 = qg * 8, k0 = kg * 8;
        float acc[8][8];
        #pragma unroll
        for (int a = 0; a < 8; a++)
            #pragma unroll
            for (int b = 0; b < 8; b++) acc[a][b] = 0.f;
        #pragma unroll
        for (int d = 0; d < 32; d++) {
            float ra[8], rb[8];
            *(float4*)(ra)     = *(float4*)(&q_s[d * QS_STR + q0]);
            *(float4*)(ra + 4) = *(float4*)(&q_s[d * QS_STR + q0 + 4]);
            *(float4*)(rb)     = *(float4*)(&k_s[d * KS_STR + k0]);
            *(float4*)(rb + 4) = *(float4*)(&k_s[d * KS_STR + k0 + 4]);
            #pragma unroll
            for (int a = 0; a < 8; a++)
                #pragma unroll
                for (int b = 0; b < 8; b++)
                    acc[a][b] += ra[a] * rb[b];
        }
        // add tri bias + mask bias, store scores
        #pragma unroll
        for (int a = 0; a < 8; a++) {
            int qglob = qt * 64 + q0 + a;
            const float* trip = g_tri + ((size_t)h * BI + qglob) * BJ + k0;
            #pragma unroll
            for (int b = 0; b < 8; b += 4) {
                float4 t4 = *(const float4*)(trip + b);
                float4 m4 = *(const float4*)(&mb_s[k0 + b]);
                s_s[(q0 + a) * SS_STR + k0 + b + 0] = acc[a][b + 0] + t4.x + m4.x;
                s_s[(q0 + a) * SS_STR + k0 + b + 1] = acc[a][b + 1] + t4.y + m4.y;
                s_s[(q0 + a) * SS_STR + k0 + b + 2] = acc[a][b + 2] + t4.z + m4.z;
                s_s[(q0 + a) * SS_STR + k0 + b + 3] = acc[a][b + 3] + t4.w + m4.w;
            }
        }
    }
    __syncthreads();

    // softmax: 4 threads per row (64 elems each)
    {
        int r = tid >> 2, part = tid & 3;
        float* row = &s_s[r * SS_STR + part * 64];
        float mx = -1e30f;
        #pragma unroll 8
        for (int n = 0; n < 64; n++) mx = fmaxf(mx, row[n]);
        mx = fmaxf(mx, __shfl_xor_sync(0xffffffffu, mx, 1));
        mx = fmaxf(mx, __shfl_xor_sync(0xffffffffu, mx, 2));
        float sum = 0.f;
        #pragma unroll 8
        for (int n = 0; n < 64; n++) {
            float e = __expf(row[n] - mx);
            row[n] = e;
            sum += e;
        }
        sum += __shfl_xor_sync(0xffffffffu, sum, 1);
        sum += __shfl_xor_sync(0xffffffffu, sum, 2);
        float inv = 1.0f / sum;
        #pragma unroll 8
        for (int n = 0; n < 64; n++) row[n] *= inv;
    }
    __syncthreads();

    // AV: 2q x 4d per thread, then gate (sigmoid) and store
    {
        int qgrp = tid >> 3;               // 0..31
        int dgrp = tid & 7;                // 0..7
        int q0 = qgrp * 2, d0 = dgrp * 4;
        float o0x = 0.f, o0y = 0.f, o0z = 0.f, o0w = 0.f;
        float o1x = 0.f, o1y = 0.f, o1z = 0.f, o1w = 0.f;
        const float* a0p = &s_s[(size_t)q0 * SS_STR];
        const float* a1p = &s_s[(size_t)(q0 + 1) * SS_STR];
        #pragma unroll 4
        for (int k = 0; k < 256; k++) {
            float a0 = a0p[k];
            float a1 = a1p[k];
            float4 v4 = *(const float4*)(&v_s[k * 32 + d0]);
            o0x += a0 * v4.x; o0y += a0 * v4.y; o0z += a0 * v4.z; o0w += a0 * v4.w;
            o1x += a1 * v4.x; o1y += a1 * v4.y; o1z += a1 * v4.z; o1w += a1 * v4.w;
        }
        #pragma unroll
        for (int qq = 0; qq < 2; qq++) {
            int jq = qt * 64 + q0 + qq;
            size_t base = ((size_t)(i * BJ + jq) * HH + h) * CH + d0;
            float4 gv = *(const float4*)(g_g + base);
            float4 out;
            float sx = 1.0f / (1.0f + __expf(-gv.x));
            float sy = 1.0f / (1.0f + __expf(-gv.y));
            float sz = 1.0f / (1.0f + __expf(-gv.z));
            float sw = 1.0f / (1.0f + __expf(-gv.w));
            if (qq == 0) { out.x = o0x * sx; out.y = o0y * sy; out.z = o0z * sz; out.w = o0w * sw; }
            else         { out.x = o1x * sx; out.y = o1y * sy; out.z = o1z * sz; out.w = o1w * sw; }
            *(float4*)(g_o + base) = out;
        }
    }
}

// ---------------- launch ----------------
extern "C" void kernel_launch(void* const* d_in, const int* in_sizes, int n_in,
                              void* d_out, int out_size) {
    const float* x     = (const float*)d_in[0];
    const float* mask  = (const float*)d_in[1];
    // d_in[2] = chunk_size (int, unused; 0 == full)
    const float* ln_w  = (const float*)d_in[3];
    const float* ln_b  = (const float*)d_in[4];
    const float* w_tri = (const float*)d_in[5];
    const float* wq    = (const float*)d_in[6];
    const float* wk    = (const float*)d_in[7];
    const float* wv    = (const float*)d_in[8];
    const float* wg    = (const float*)d_in[9];
    const float* bg    = (const float*)d_in[10];
    const float* wo    = (const float*)d_in[11];
    const float* bo    = (const float*)d_in[12];
    float* out = (float*)d_out;

    float *xn_p, *q_p, *k_p, *v_p, *g_p, *o_p;
    cudaGetSymbolAddress((void**)&xn_p, g_xn);
    cudaGetSymbolAddress((void**)&q_p,  g_q);
    cudaGetSymbolAddress((void**)&k_p,  g_k);
    cudaGetSymbolAddress((void**)&v_p,  g_v);
    cudaGetSymbolAddress((void**)&g_p,  g_g);
    cudaGetSymbolAddress((void**)&o_p,  g_o);

    ln_kernel<<<MROWS, 128>>>(x, ln_w, ln_b);
    tri_kernel<<<MROWS / 8, 256>>>(w_tri);

    const float qscale = 0.17677669529663687f;  // 32^-0.5
    gemm_nn_k128<<<MROWS / 128, 256>>>(xn_p, wq, q_p, qscale, nullptr);
    gemm_nn_k128<<<MROWS / 128, 256>>>(xn_p, wk, k_p, 1.0f, nullptr);
    gemm_nn_k128<<<MROWS / 128, 256>>>(xn_p, wv, v_p, 1.0f, nullptr);
    gemm_nn_k128<<<MROWS / 128, 256>>>(xn_p, wg, g_p, 1.0f, bg);

    cudaFuncSetAttribute(attn_kernel, cudaFuncAttributeMaxDynamicSharedMemorySize,
                         ATTN_SMEM_FLOATS * (int)sizeof(float));
    dim3 agrid(4, HH, BI);
    attn_kernel<<<agrid, 256, ATTN_SMEM_FLOATS * sizeof(float)>>>(mask);

    gemm_nn_k128<<<MROWS / 128, 256>>>(o_p, wo, out, 1.0f, bo);
}

// round 4
// speedup vs baseline: 1.0023x; 1.0023x over previous
#include <cuda_runtime.h>
#include <cuda_bf16.h>
#include <math.h>

// Problem dims (fixed)
#define BI   256          // I
#define BJ   256          // J
#define CC   128          // C
#define HH   4            // heads
#define CH   32           // per-head dim
#define MROWS (BI*BJ)     // 65536

// ---------------- scratch (device globals; no allocation) ----------------
__device__ float g_xn[(size_t)MROWS * CC];
__device__ float g_q [(size_t)MROWS * CC];
__device__ float g_k [(size_t)MROWS * CC];
__device__ float g_v [(size_t)MROWS * CC];
__device__ float g_g [(size_t)MROWS * CC];
__device__ float g_tri[(size_t)HH * BI * BJ];
__device__ float g_o [(size_t)MROWS * CC];

// ---------------- LayerNorm: one block (128 thr) per row ----------------
__global__ void ln_kernel(const float* __restrict__ x,
                          const float* __restrict__ w,
                          const float* __restrict__ b) {
    int row = blockIdx.x;
    int t = threadIdx.x;
    float v = x[(size_t)row * CC + t];
    float s = v, sq = v * v;
    #pragma unroll
    for (int off = 16; off; off >>= 1) {
        s  += __shfl_xor_sync(0xffffffffu, s,  off);
        sq += __shfl_xor_sync(0xffffffffu, sq, off);
    }
    __shared__ float sh[8];
    int wid = t >> 5, lane = t & 31;
    if (lane == 0) { sh[wid] = s; sh[4 + wid] = sq; }
    __syncthreads();
    s  = sh[0] + sh[1] + sh[2] + sh[3];
    sq = sh[4] + sh[5] + sh[6] + sh[7];
    float mu  = s * (1.0f / CC);
    float var = sq * (1.0f / CC) - mu * mu;
    float rs  = rsqrtf(var + 1e-5f);
    g_xn[(size_t)row * CC + t] = (v - mu) * rs * w[t] + b[t];
}

// ---------------- tri bias: tri[h][i][j] = xn[i,j,:] . w_tri[:,h] --------
__global__ void tri_kernel(const float* __restrict__ w_tri) {
    int row  = blockIdx.x * 8 + (threadIdx.x >> 5);   // 0..65535
    int lane = threadIdx.x & 31;
    float a0 = 0.f, a1 = 0.f, a2 = 0.f, a3 = 0.f;
    #pragma unroll
    for (int c0 = 0; c0 < CC; c0 += 32) {
        float xv = g_xn[(size_t)row * CC + c0 + lane];
        float4 w = *(const float4*)(w_tri + (size_t)(c0 + lane) * 4);
        a0 += xv * w.x; a1 += xv * w.y; a2 += xv * w.z; a3 += xv * w.w;
    }
    #pragma unroll
    for (int off = 16; off; off >>= 1) {
        a0 += __shfl_xor_sync(0xffffffffu, a0, off);
        a1 += __shfl_xor_sync(0xffffffffu, a1, off);
        a2 += __shfl_xor_sync(0xffffffffu, a2, off);
        a3 += __shfl_xor_sync(0xffffffffu, a3, off);
    }
    if (lane == 0) {
        g_tri[0 * (size_t)MROWS + row] = a0;
        g_tri[1 * (size_t)MROWS + row] = a1;
        g_tri[2 * (size_t)MROWS + row] = a2;
        g_tri[3 * (size_t)MROWS + row] = a3;
    }
}

// ---------------- SGEMM: C[M,128] = alpha * A[M,128] @ B[128,128] + bias --
// 128x128 block tile, 8x8 per thread, 256 threads.
__global__ void __launch_bounds__(256)
gemm_nn_k128(const float* __restrict__ A, const float* __restrict__ B,
             float* __restrict__ C, float alpha, const float* __restrict__ bias) {
    __shared__ float As[16][132];   // transposed A tile: As[k][m], padded
    __shared__ float Bs[16][128];
    int tid = threadIdx.x;
    int m0  = blockIdx.x * 128;
    int ty  = tid >> 4, tx = tid & 15;   // 16x16 thread grid
    float acc[8][8];
    #pragma unroll
    for (int a = 0; a < 8; a++)
        #pragma unroll
        for (int b = 0; b < 8; b++) acc[a][b] = 0.f;

    for (int k0 = 0; k0 < 128; k0 += 16) {
        // A tile: 128 rows x 16 k = 512 float4
        #pragma unroll
        for (int l = 0; l < 2; l++) {
            int idx = tid + l * 256;
            int ar = idx >> 2;          // 0..127
            int ac = (idx & 3) * 4;     // 0,4,8,12
            float4 f = *(const float4*)(A + (size_t)(m0 + ar) * 128 + k0 + ac);
            As[ac + 0][ar] = f.x;
            As[ac + 1][ar] = f.y;
            As[ac + 2][ar] = f.z;
            As[ac + 3][ar] = f.w;
        }
        // B tile: 16 rows x 128 = 512 float4
        #pragma unroll
        for (int l = 0; l < 2; l++) {
            int idx = tid + l * 256;
            int br = idx >> 5;          // 0..15
            int bc = (idx & 31) * 4;    // 0..124
            *(float4*)(&Bs[br][bc]) = *(const float4*)(B + (size_t)(k0 + br) * 128 + bc);
        }
        __syncthreads();
        #pragma unroll
        for (int kk = 0; kk < 16; kk++) {
            float ra[8], rb[8];
            *(float4*)(ra)     = *(float4*)(&As[kk][ty * 8]);
            *(float4*)(ra + 4) = *(float4*)(&As[kk][ty * 8 + 4]);
            *(float4*)(rb)     = *(float4*)(&Bs[kk][tx * 8]);
            *(float4*)(rb + 4) = *(float4*)(&Bs[kk][tx * 8 + 4]);
            #pragma unroll
            for (int a = 0; a < 8; a++)
                #pragma unroll
                for (int b = 0; b < 8; b++)
                    acc[a][b] += ra[a] * rb[b];
        }
        __syncthreads();
    }
    #pragma unroll
    for (int a = 0; a < 8; a++) {
        int m = m0 + ty * 8 + a;
        #pragma unroll
        for (int b = 0; b < 8; b += 4) {
            int n = tx * 8 + b;
            float4 o;
            o.x = alpha * acc[a][b + 0] + (bias ? bias[n + 0] : 0.f);
            o.y = alpha * acc[a][b + 1] + (bias ? bias[n + 1] : 0.f);
            o.z = alpha * acc[a][b + 2] + (bias ? bias[n + 2] : 0.f);
            o.w = alpha * acc[a][b + 3] + (bias ? bias[n + 3] : 0.f);
            *(float4*)(C + (size_t)m * 128 + n) = o;
        }
    }
}

// ---------------- attention: block per (qtile=64, h, i) ------------------
// smem: q_s[32][68] (d-major), k_s[32][260] (d-major), v_s[256][32],
//       s_s[64][260], mb_s[256]
#define QS_STR 68
#define KS_STR 260
#define SS_STR 260
#define SM_Q   0
#define SM_K   (SM_Q + 32 * QS_STR)
#define SM_V   (SM_K + 32 * KS_STR)
#define SM_S   (SM_V + 256 * 32)
#define SM_MB  (SM_S + 64 * SS_STR)
#define ATTN_SMEM_FLOATS (SM_MB + 256)

__global__ void __launch_bounds__(256)
attn_kernel(const float* __restrict__ mask) {
    extern __shared__ float sm[];
    float* q_s  = sm + SM_Q;
    float* k_s  = sm + SM_K;
    float* v_s  = sm + SM_V;
    float* s_s  = sm + SM_S;
    float* mb_s = sm + SM_MB;

    int tid = threadIdx.x;
    int qt = blockIdx.x;       // 0..3 (q tile of 64)
    int h  = blockIdx.y;       // 0..3
    int i  = blockIdx.z;       // 0..255

    mb_s[tid] = 1.0e9f * (mask[(size_t)i * BJ + tid] - 1.0f);

    // q tile (transposed to d-major)
    #pragma unroll
    for (int l = 0; l < 2; l++) {
        int idx = tid + l * 256;
        int jr = idx >> 3;                 // 0..63
        int d4 = (idx & 7) * 4;
        int jg = qt * 64 + jr;
        float4 f = *(const float4*)(g_q + (((size_t)(i * BJ + jg) * HH + h) * CH) + d4);
        q_s[(d4 + 0) * QS_STR + jr] = f.x;
        q_s[(d4 + 1) * QS_STR + jr] = f.y;
        q_s[(d4 + 2) * QS_STR + jr] = f.z;
        q_s[(d4 + 3) * QS_STR + jr] = f.w;
    }
    // k (transposed), v (natural)
    #pragma unroll
    for (int l = 0; l < 8; l++) {
        int idx = tid + l * 256;
        int jr = idx >> 3;                 // 0..255
        int d4 = (idx & 7) * 4;
        size_t base = ((size_t)(i * BJ + jr) * HH + h) * CH + d4;
        float4 fk = *(const float4*)(g_k + base);
        k_s[(d4 + 0) * KS_STR + jr] = fk.x;
        k_s[(d4 + 1) * KS_STR + jr] = fk.y;
        k_s[(d4 + 2) * KS_STR + jr] = fk.z;
        k_s[(d4 + 3) * KS_STR + jr] = fk.w;
        *(float4*)(&v_s[jr * 32 + d4]) = *(const float4*)(g_v + base);
    }
    __syncthreads();

    // scores: 8q x 8k per thread (q-group uniform per warp -> broadcast LDS)
    {
        int qg = tid >> 5;         // 0..7
        int kg = tid & 31;         // 0..31
        int q0 = qg * 8, k0 = kg * 8;
        float acc[8][8];
        #pragma unroll
        for (int a = 0; a < 8; a++)
            #pragma unroll
            for (int b = 0; b < 8; b++) acc[a][b] = 0.f;
        #pragma unroll
        for (int d = 0; d < 32; d++) {
            float ra[8], rb[8];
            *(float4*)(ra)     = *(float4*)(&q_s[d * QS_STR + q0]);
            *(float4*)(ra + 4) = *(float4*)(&q_s[d * QS_STR + q0 + 4]);
            *(float4*)(rb)     = *(float4*)(&k_s[d * KS_STR + k0]);
            *(float4*)(rb + 4) = *(float4*)(&k_s[d * KS_STR + k0 + 4]);
            #pragma unroll
            for (int a = 0; a < 8; a++)
                #pragma unroll
                for (int b = 0; b < 8; b++)
                    acc[a][b] += ra[a] * rb[b];
        }
        // add tri bias + mask bias, store scores
        #pragma unroll
        for (int a = 0; a < 8; a++) {
            int qglob = qt * 64 + q0 + a;
            const float* trip = g_tri + ((size_t)h * BI + qglob) * BJ + k0;
            #pragma unroll
            for (int b = 0; b < 8; b += 4) {
                float4 t4 = *(const float4*)(trip + b);
                float4 m4 = *(const float4*)(&mb_s[k0 + b]);
                s_s[(q0 + a) * SS_STR + k0 + b + 0] = acc[a][b + 0] + t4.x + m4.x;
                s_s[(q0 + a) * SS_STR + k0 + b + 1] = acc[a][b + 1] + t4.y + m4.y;
                s_s[(q0 + a) * SS_STR + k0 + b + 2] = acc[a][b + 2] + t4.z + m4.z;
                s_s[(q0 + a) * SS_STR + k0 + b + 3] = acc[a][b + 3] + t4.w + m4.w;
            }
        }
    }
    __syncthreads();

    // softmax: 4 threads per row (64 elems each)
    {
        int r = tid >> 2, part = tid & 3;
        float* row = &s_s[r * SS_STR + part * 64];
        float mx = -1e30f;
        #pragma unroll 8
        for (int n = 0; n < 64; n++) mx = fmaxf(mx, row[n]);
        mx = fmaxf(mx, __shfl_xor_sync(0xffffffffu, mx, 1));
        mx = fmaxf(mx, __shfl_xor_sync(0xffffffffu, mx, 2));
        float sum = 0.f;
        #pragma unroll 8
        for (int n = 0; n < 64; n++) {
            float e = __expf(row[n] - mx);
            row[n] = e;
            sum += e;
        }
        sum += __shfl_xor_sync(0xffffffffu, sum, 1);
        sum += __shfl_xor_sync(0xffffffffu, sum, 2);
        float inv = 1.0f / sum;
        #pragma unroll 8
        for (int n = 0; n < 64; n++) row[n] *= inv;
    }
    __syncthreads();

    // AV: 2q x 4d per thread, then gate (sigmoid) and store
    {
        int qgrp = tid >> 3;               // 0..31
        int dgrp = tid & 7;                // 0..7
        int q0 = qgrp * 2, d0 = dgrp * 4;
        float o0x = 0.f, o0y = 0.f, o0z = 0.f, o0w = 0.f;
        float o1x = 0.f, o1y = 0.f, o1z = 0.f, o1w = 0.f;
        const float* a0p = &s_s[(size_t)q0 * SS_STR];
        const float* a1p = &s_s[(size_t)(q0 + 1) * SS_STR];
        #pragma unroll 4
        for (int k = 0; k < 256; k++) {
            float a0 = a0p[k];
            float a1 = a1p[k];
            float4 v4 = *(const float4*)(&v_s[k * 32 + d0]);
            o0x += a0 * v4.x; o0y += a0 * v4.y; o0z += a0 * v4.z; o0w += a0 * v4.w;
            o1x += a1 * v4.x; o1y += a1 * v4.y; o1z += a1 * v4.z; o1w += a1 * v4.w;
        }
        #pragma unroll
        for (int qq = 0; qq < 2; qq++) {
            int jq = qt * 64 + q0 + qq;
            size_t base = ((size_t)(i * BJ + jq) * HH + h) * CH + d0;
            float4 gv = *(const float4*)(g_g + base);
            float4 out;
            float sx = 1.0f / (1.0f + __expf(-gv.x));
            float sy = 1.0f / (1.0f + __expf(-gv.y));
            float sz = 1.0f / (1.0f + __expf(-gv.z));
            float sw = 1.0f / (1.0f + __expf(-gv.w));
            if (qq == 0) { out.x = o0x * sx; out.y = o0y * sy; out.z = o0z * sz; out.w = o0w * sw; }
            else         { out.x = o1x * sx; out.y = o1y * sy; out.z = o1z * sz; out.w = o1w * sw; }
            *(float4*)(g_o + base) = out;
        }
    }
}

// ---------------- launch ----------------
extern "C" void kernel_launch(void* const* d_in, const int* in_sizes, int n_in,
                              void* d_out, int out_size) {
    const float* x     = (const float*)d_in[0];
    const float* mask  = (const float*)d_in[1];
    // d_in[2] = chunk_size (int, unused; 0 == full)
    const float* ln_w  = (const float*)d_in[3];
    const float* ln_b  = (const float*)d_in[4];
    const float* w_tri = (const float*)d_in[5];
    const float* wq    = (const float*)d_in[6];
    const float* wk    = (const float*)d_in[7];
    const float* wv    = (const float*)d_in[8];
    const float* wg    = (const float*)d_in[9];
    const float* bg    = (const float*)d_in[10];
    const float* wo    = (const float*)d_in[11];
    const float* bo    = (const float*)d_in[12];
    float* out = (float*)d_out;

    float *xn_p, *q_p, *k_p, *v_p, *g_p, *o_p;
    cudaGetSymbolAddress((void**)&xn_p, g_xn);
    cudaGetSymbolAddress((void**)&q_p,  g_q);
    cudaGetSymbolAddress((void**)&k_p,  g_k);
    cudaGetSymbolAddress((void**)&v_p,  g_v);
    cudaGetSymbolAddress((void**)&g_p,  g_g);
    cudaGetSymbolAddress((void**)&o_p,  g_o);

    ln_kernel<<<MROWS, 128>>>(x, ln_w, ln_b);
    tri_kernel<<<MROWS / 8, 256>>>(w_tri);

    const float qscale = 0.17677669529663687f;  // 32^-0.5
    gemm_nn_k128<<<MROWS / 128, 256>>>(xn_p, wq, q_p, qscale, nullptr);
    gemm_nn_k128<<<MROWS / 128, 256>>>(xn_p, wk, k_p, 1.0f, nullptr);
    gemm_nn_k128<<<MROWS / 128, 256>>>(xn_p, wv, v_p, 1.0f, nullptr);
    gemm_nn_k128<<<MROWS / 128, 256>>>(xn_p, wg, g_p, 1.0f, bg);

    cudaFuncSetAttribute(attn_kernel, cudaFuncAttributeMaxDynamicSharedMemorySize,
                         ATTN_SMEM_FLOATS * (int)sizeof(float));
    dim3 agrid(4, HH, BI);
    attn_kernel<<<agrid, 256, ATTN_SMEM_FLOATS * sizeof(float)>>>(mask);

    gemm_nn_k128<<<MROWS / 128, 256>>>(o_p, wo, out, 1.0f, bo);
}

// round 5
// speedup vs baseline: 1.9494x; 1.9450x over previous
#include <cuda_runtime.h>
#include <cuda_bf16.h>
#include <math.h>

// Problem dims (fixed)
#define BI   256          // I
#define BJ   256          // J
#define CC   128          // C
#define HH   4            // heads
#define CH   32           // per-head dim
#define MROWS (BI*BJ)     // 65536

// ---------------- scratch (device globals; no allocation) ----------------
__device__ float g_xn[(size_t)MROWS * CC];
__device__ float g_q [(size_t)MROWS * CC];
__device__ float g_k [(size_t)MROWS * CC];
__device__ float g_v [(size_t)MROWS * CC];
__device__ float g_g [(size_t)MROWS * CC];
__device__ float g_tri[(size_t)HH * BI * BJ];
__device__ float g_o [(size_t)MROWS * CC];

// ---------------- tf32 helpers ----------------
__device__ __forceinline__ unsigned cvt_tf32(float f) {
    unsigned u;
    asm("cvt.rna.tf32.f32 %0, %1;" : "=r"(u) : "f"(f));
    return u;
}

__device__ __forceinline__ void mma_tf32(float &d0, float &d1, float &d2, float &d3,
                                         unsigned a0, unsigned a1, unsigned a2, unsigned a3,
                                         unsigned b0, unsigned b1) {
    asm volatile(
        "mma.sync.aligned.m16n8k8.row.col.f32.tf32.tf32.f32 "
        "{%0,%1,%2,%3}, {%4,%5,%6,%7}, {%8,%9}, {%0,%1,%2,%3};"
        : "+f"(d0), "+f"(d1), "+f"(d2), "+f"(d3)
        : "r"(a0), "r"(a1), "r"(a2), "r"(a3), "r"(b0), "r"(b1));
}

// ---------------- LayerNorm + tri bias fused: one block (128 thr) per row --
__global__ void ln_tri_kernel(const float* __restrict__ x,
                              const float* __restrict__ w,
                              const float* __restrict__ b,
                              const float* __restrict__ w_tri) {
    int row = blockIdx.x;
    int t = threadIdx.x;
    float v = x[(size_t)row * CC + t];
    float s = v, sq = v * v;
    #pragma unroll
    for (int off = 16; off; off >>= 1) {
        s  += __shfl_xor_sync(0xffffffffu, s,  off);
        sq += __shfl_xor_sync(0xffffffffu, sq, off);
    }
    __shared__ float sh[8];
    __shared__ float sh2[4][4];
    int wid = t >> 5, lane = t & 31;
    if (lane == 0) { sh[wid] = s; sh[4 + wid] = sq; }
    __syncthreads();
    s  = sh[0] + sh[1] + sh[2] + sh[3];
    sq = sh[4] + sh[5] + sh[6] + sh[7];
    float mu  = s * (1.0f / CC);
    float var = sq * (1.0f / CC) - mu * mu;
    float rs  = rsqrtf(var + 1e-5f);
    float xn = (v - mu) * rs * w[t] + b[t];
    g_xn[(size_t)row * CC + t] = xn;

    // tri: dot(xn_row, w_tri[:,h]) for h=0..3
    float4 wt = ((const float4*)w_tri)[t];     // w_tri[t][0..3]
    float p0 = xn * wt.x, p1 = xn * wt.y, p2 = xn * wt.z, p3 = xn * wt.w;
    #pragma unroll
    for (int off = 16; off; off >>= 1) {
        p0 += __shfl_xor_sync(0xffffffffu, p0, off);
        p1 += __shfl_xor_sync(0xffffffffu, p1, off);
        p2 += __shfl_xor_sync(0xffffffffu, p2, off);
        p3 += __shfl_xor_sync(0xffffffffu, p3, off);
    }
    if (lane == 0) {
        sh2[wid][0] = p0; sh2[wid][1] = p1; sh2[wid][2] = p2; sh2[wid][3] = p3;
    }
    __syncthreads();
    if (t < 4) {
        float acc = sh2[0][t] + sh2[1][t] + sh2[2][t] + sh2[3][t];
        g_tri[(size_t)t * MROWS + row] = acc;
    }
}

// ---------------- tf32 GEMM: C[M,128] = alpha*A[M,128]@B[128,128] + bias ---
// 128x128 block tile, 256 threads = 8 warps (2 along M x 4 along N).
// Warp tile 64x32: 4 m16-tiles x 4 n8-tiles, mma m16n8k8 tf32.
// A staged in smem (tf32, stride 68 -> conflict-free frag loads).
// B fragments loaded straight from gmem (64KB matrix, L1/L2 resident).
#define AS_STR 68
__global__ void __launch_bounds__(256)
gemm_tf32(const float* __restrict__ A, const float* __restrict__ B,
          float* __restrict__ C, float alpha, const float* __restrict__ bias) {
    __shared__ unsigned As[128 * AS_STR];
    int tid  = threadIdx.x;
    int warp = tid >> 5, lane = tid & 31;
    int wm = warp >> 2, wn = warp & 3;       // wm 0..1, wn 0..3
    int m0 = blockIdx.x * 128;

    float4 acc[4][4];
    #pragma unroll
    for (int a = 0; a < 4; a++)
        #pragma unroll
        for (int b = 0; b < 4; b++) acc[a][b] = make_float4(0.f, 0.f, 0.f, 0.f);

    for (int kc = 0; kc < 128; kc += 64) {
        // stage A chunk 128x64 as tf32
        #pragma unroll
        for (int l = 0; l < 8; l++) {
            int idx = tid + l * 256;
            int mr = idx >> 4;
            int k4 = (idx & 15) * 4;
            float4 f = *(const float4*)(A + (size_t)(m0 + mr) * 128 + kc + k4);
            uint4 u;
            u.x = cvt_tf32(f.x); u.y = cvt_tf32(f.y);
            u.z = cvt_tf32(f.z); u.w = cvt_tf32(f.w);
            *(uint4*)(As + mr * AS_STR + k4) = u;
        }
        __syncthreads();

        #pragma unroll
        for (int ks = 0; ks < 8; ks++) {
            int kk = ks * 8;
            unsigned af[4][4];
            #pragma unroll
            for (int mi = 0; mi < 4; mi++) {
                int r = wm * 64 + mi * 16 + (lane >> 2);
                int c = kk + (lane & 3);
                af[mi][0] = As[r * AS_STR + c];
                af[mi][1] = As[(r + 8) * AS_STR + c];
                af[mi][2] = As[r * AS_STR + c + 4];
                af[mi][3] = As[(r + 8) * AS_STR + c + 4];
            }
            const float* Bp = B + (size_t)(kc + kk + (lane & 3)) * 128 + wn * 32 + (lane >> 2);
            #pragma unroll
            for (int ni = 0; ni < 4; ni++) {
                unsigned b0 = cvt_tf32(Bp[ni * 8]);
                unsigned b1 = cvt_tf32(Bp[4 * 128 + ni * 8]);
                #pragma unroll
                for (int mi = 0; mi < 4; mi++)
                    mma_tf32(acc[mi][ni].x, acc[mi][ni].y, acc[mi][ni].z, acc[mi][ni].w,
                             af[mi][0], af[mi][1], af[mi][2], af[mi][3], b0, b1);
            }
        }
        __syncthreads();
    }

    // store: c-frag mapping (row = lane/4 (+8), col = 2*(lane%3... lane&3))
    #pragma unroll
    for (int mi = 0; mi < 4; mi++) {
        int r = m0 + wm * 64 + mi * 16 + (lane >> 2);
        #pragma unroll
        for (int ni = 0; ni < 4; ni++) {
            int c = wn * 32 + ni * 8 + 2 * (lane & 3);
            float bx = bias ? bias[c] : 0.f;
            float by = bias ? bias[c + 1] : 0.f;
            float2 lo = make_float2(acc[mi][ni].x * alpha + bx, acc[mi][ni].y * alpha + by);
            float2 hi = make_float2(acc[mi][ni].z * alpha + bx, acc[mi][ni].w * alpha + by);
            *(float2*)(C + (size_t)r * 128 + c) = lo;
            *(float2*)(C + (size_t)(r + 8) * 128 + c) = hi;
        }
    }
}

// ---------------- attention: block per (qtile=64, h, i), 512 threads -----
// smem (floats): q[64][36] tf32, k[256][36] tf32, v[256][40] tf32,
//                s[64][260] fp32 scores (tf32 bits after softmax), mb[256]
#define QS_STR 36
#define KS_STR 36
#define VS_STR 40
#define SS_STR 260
#define SM_Q   0
#define SM_K   (SM_Q + 64 * QS_STR)
#define SM_V   (SM_K + 256 * KS_STR)
#define SM_S   (SM_V + 256 * VS_STR)
#define SM_MB  (SM_S + 64 * SS_STR)
#define ATTN_SMEM_FLOATS (SM_MB + 256)

__global__ void __launch_bounds__(512)
attn_kernel(const float* __restrict__ mask) {
    extern __shared__ float sm[];
    unsigned* q_su = (unsigned*)(sm + SM_Q);
    unsigned* k_su = (unsigned*)(sm + SM_K);
    unsigned* v_su = (unsigned*)(sm + SM_V);
    float*    s_s  = sm + SM_S;
    float*    mb_s = sm + SM_MB;

    int tid = threadIdx.x;
    int warp = tid >> 5, lane = tid & 31;
    int qt = blockIdx.x;       // 0..3
    int h  = blockIdx.y;       // 0..3
    int i  = blockIdx.z;       // 0..255

    if (tid < 256) mb_s[tid] = 1.0e9f * (mask[(size_t)i * BJ + tid] - 1.0f);

    // ---- fill q (64x32), k (256x32), v (256x32) as tf32 ----
    {
        int jr = tid >> 3, d4 = (tid & 7) * 4;
        int jg = qt * 64 + jr;
        float4 f = *(const float4*)(g_q + ((size_t)(i * BJ + jg) * HH + h) * CH + d4);
        uint4 u;
        u.x = cvt_tf32(f.x); u.y = cvt_tf32(f.y); u.z = cvt_tf32(f.z); u.w = cvt_tf32(f.w);
        *(uint4*)(q_su + jr * QS_STR + d4) = u;
    }
    #pragma unroll
    for (int l2 = 0; l2 < 4; l2++) {
        int idx = tid + l2 * 512;
        int jr = idx >> 3, d4 = (idx & 7) * 4;
        size_t base = ((size_t)(i * BJ + jr) * HH + h) * CH + d4;
        float4 fk = *(const float4*)(g_k + base);
        uint4 uk;
        uk.x = cvt_tf32(fk.x); uk.y = cvt_tf32(fk.y); uk.z = cvt_tf32(fk.z); uk.w = cvt_tf32(fk.w);
        *(uint4*)(k_su + jr * KS_STR + d4) = uk;
        float4 fv = *(const float4*)(g_v + base);
        uint4 uv;
        uv.x = cvt_tf32(fv.x); uv.y = cvt_tf32(fv.y); uv.z = cvt_tf32(fv.z); uv.w = cvt_tf32(fv.w);
        *(uint4*)(v_su + jr * VS_STR + d4) = uv;
    }
    __syncthreads();

    // ---- QK^T: M=64, N=256, K=32. 16 warps: 4(M) x 4(N), warp 16x64 ----
    {
        int m0w = (warp >> 2) * 16;
        int n0w = (warp & 3) * 64;
        float4 acc[8];
        #pragma unroll
        for (int nt = 0; nt < 8; nt++) acc[nt] = make_float4(0.f, 0.f, 0.f, 0.f);

        #pragma unroll
        for (int ks = 0; ks < 4; ks++) {
            int kk = ks * 8;
            int ar = m0w + (lane >> 2);
            int cA = kk + (lane & 3);
            unsigned a0 = q_su[ar * QS_STR + cA];
            unsigned a1 = q_su[(ar + 8) * QS_STR + cA];
            unsigned a2 = q_su[ar * QS_STR + cA + 4];
            unsigned a3 = q_su[(ar + 8) * QS_STR + cA + 4];
            #pragma unroll
            for (int nt = 0; nt < 8; nt++) {
                int n = n0w + nt * 8 + (lane >> 2);
                unsigned b0 = k_su[n * KS_STR + kk + (lane & 3)];
                unsigned b1 = k_su[n * KS_STR + kk + 4 + (lane & 3)];
                mma_tf32(acc[nt].x, acc[nt].y, acc[nt].z, acc[nt].w,
                         a0, a1, a2, a3, b0, b1);
            }
        }
        // epilogue: + tri bias + mask bias -> s_s
        int r0 = m0w + (lane >> 2);
        int qg = qt * 64 + r0;
        #pragma unroll
        for (int nt = 0; nt < 8; nt++) {
            int c = n0w + nt * 8 + 2 * (lane & 3);
            float2 t0  = *(const float2*)(g_tri + ((size_t)h * BI + qg) * BJ + c);
            float2 t1  = *(const float2*)(g_tri + ((size_t)h * BI + qg + 8) * BJ + c);
            float2 mbv = *(const float2*)(mb_s + c);
            s_s[r0 * SS_STR + c]           = acc[nt].x + t0.x + mbv.x;
            s_s[r0 * SS_STR + c + 1]       = acc[nt].y + t0.y + mbv.y;
            s_s[(r0 + 8) * SS_STR + c]     = acc[nt].z + t1.x + mbv.x;
            s_s[(r0 + 8) * SS_STR + c + 1] = acc[nt].w + t1.y + mbv.y;
        }
    }
    __syncthreads();

    // ---- softmax: warp-per-row, lane-strided scalar (conflict-free) ----
    {
        #pragma unroll
        for (int rr = 0; rr < 4; rr++) {
            int r = warp * 4 + rr;
            float* row = s_s + r * SS_STR;
            float e[8];
            float mx = -1e30f;
            #pragma unroll
            for (int t = 0; t < 8; t++) { e[t] = row[lane + 32 * t]; mx = fmaxf(mx, e[t]); }
            #pragma unroll
            for (int off = 16; off; off >>= 1)
                mx = fmaxf(mx, __shfl_xor_sync(0xffffffffu, mx, off));
            float sum = 0.f;
            #pragma unroll
            for (int t = 0; t < 8; t++) { e[t] = __expf(e[t] - mx); sum += e[t]; }
            #pragma unroll
            for (int off = 16; off; off >>= 1)
                sum += __shfl_xor_sync(0xffffffffu, sum, off);
            float inv = 1.0f / sum;
            unsigned* rowu = (unsigned*)row;
            #pragma unroll
            for (int t = 0; t < 8; t++) rowu[lane + 32 * t] = cvt_tf32(e[t] * inv);
        }
    }
    __syncthreads();

    // ---- AV: M=64, N=32, K=256. 16 warps: 4(M) x 4(N), warp 16x8 ----
    {
        int m0 = (warp >> 2) * 16;
        int n0 = (warp & 3) * 8;
        float4 acc = make_float4(0.f, 0.f, 0.f, 0.f);
        const unsigned* s_su = (const unsigned*)s_s;
        #pragma unroll 8
        for (int ks = 0; ks < 32; ks++) {
            int kk = ks * 8;
            int ar = m0 + (lane >> 2);
            int cA = kk + (lane & 3);
            unsigned a0 = s_su[ar * SS_STR + cA];
            unsigned a1 = s_su[(ar + 8) * SS_STR + cA];
            unsigned a2 = s_su[ar * SS_STR + cA + 4];
            unsigned a3 = s_su[(ar + 8) * SS_STR + cA + 4];
            int n = n0 + (lane >> 2);
            unsigned b0 = v_su[(kk + (lane & 3)) * VS_STR + n];
            unsigned b1 = v_su[(kk + 4 + (lane & 3)) * VS_STR + n];
            mma_tf32(acc.x, acc.y, acc.z, acc.w, a0, a1, a2, a3, b0, b1);
        }
        // gate (sigmoid) + store
        int qloc = m0 + (lane >> 2);
        int d = n0 + 2 * (lane & 3);
        #pragma unroll
        for (int half = 0; half < 2; half++) {
            int jq = qt * 64 + qloc + half * 8;
            size_t base = ((size_t)(i * BJ + jq) * HH + h) * CH + d;
            float2 gv = *(const float2*)(g_g + base);
            float vx = half ? acc.z : acc.x;
            float vy = half ? acc.w : acc.y;
            float2 ov;
            ov.x = vx / (1.0f + __expf(-gv.x));
            ov.y = vy / (1.0f + __expf(-gv.y));
            *(float2*)(g_o + base) = ov;
        }
    }
}

// ---------------- launch ----------------
extern "C" void kernel_launch(void* const* d_in, const int* in_sizes, int n_in,
                              void* d_out, int out_size) {
    const float* x     = (const float*)d_in[0];
    const float* mask  = (const float*)d_in[1];
    // d_in[2] = chunk_size (unused)
    const float* ln_w  = (const float*)d_in[3];
    const float* ln_b  = (const float*)d_in[4];
    const float* w_tri = (const float*)d_in[5];
    const float* wq    = (const float*)d_in[6];
    const float* wk    = (const float*)d_in[7];
    const float* wv    = (const float*)d_in[8];
    const float* wg    = (const float*)d_in[9];
    const float* bg    = (const float*)d_in[10];
    const float* wo    = (const float*)d_in[11];
    const float* bo    = (const float*)d_in[12];
    float* out = (float*)d_out;

    float *xn_p, *q_p, *k_p, *v_p, *g_p, *o_p;
    cudaGetSymbolAddress((void**)&xn_p, g_xn);
    cudaGetSymbolAddress((void**)&q_p,  g_q);
    cudaGetSymbolAddress((void**)&k_p,  g_k);
    cudaGetSymbolAddress((void**)&v_p,  g_v);
    cudaGetSymbolAddress((void**)&g_p,  g_g);
    cudaGetSymbolAddress((void**)&o_p,  g_o);

    ln_tri_kernel<<<MROWS, 128>>>(x, ln_w, ln_b, w_tri);

    const float qscale = 0.17677669529663687f;  // 32^-0.5
    gemm_tf32<<<MROWS / 128, 256>>>(xn_p, wq, q_p, qscale, nullptr);
    gemm_tf32<<<MROWS / 128, 256>>>(xn_p, wk, k_p, 1.0f, nullptr);
    gemm_tf32<<<MROWS / 128, 256>>>(xn_p, wv, v_p, 1.0f, nullptr);
    gemm_tf32<<<MROWS / 128, 256>>>(xn_p, wg, g_p, 1.0f, bg);

    cudaFuncSetAttribute(attn_kernel, cudaFuncAttributeMaxDynamicSharedMemorySize,
                         ATTN_SMEM_FLOATS * (int)sizeof(float));
    dim3 agrid(4, HH, BI);
    attn_kernel<<<agrid, 512, ATTN_SMEM_FLOATS * sizeof(float)>>>(mask);

    gemm_tf32<<<MROWS / 128, 256>>>(o_p, wo, out, 1.0f, bo);
}

// round 6
// speedup vs baseline: 1.9498x; 1.0002x over previous
#include <cuda_runtime.h>
#include <cuda_bf16.h>
#include <math.h>

// Problem dims (fixed)
#define BI   256          // I
#define BJ   256          // J
#define CC   128          // C
#define HH   4            // heads
#define CH   32           // per-head dim
#define MROWS (BI*BJ)     // 65536

// ---------------- scratch (device globals; no allocation) ----------------
__device__ float g_xn[(size_t)MROWS * CC];
__device__ float g_q [(size_t)MROWS * CC];
__device__ float g_k [(size_t)MROWS * CC];
__device__ float g_v [(size_t)MROWS * CC];
__device__ float g_g [(size_t)MROWS * CC];
__device__ float g_tri[(size_t)HH * BI * BJ];
__device__ float g_o [(size_t)MROWS * CC];

// ---------------- tf32 helpers ----------------
__device__ __forceinline__ unsigned cvt_tf32(float f) {
    unsigned u;
    asm("cvt.rna.tf32.f32 %0, %1;" : "=r"(u) : "f"(f));
    return u;
}

__device__ __forceinline__ void mma_tf32(float &d0, float &d1, float &d2, float &d3,
                                         unsigned a0, unsigned a1, unsigned a2, unsigned a3,
                                         unsigned b0, unsigned b1) {
    asm volatile(
        "mma.sync.aligned.m16n8k8.row.col.f32.tf32.tf32.f32 "
        "{%0,%1,%2,%3}, {%4,%5,%6,%7}, {%8,%9}, {%0,%1,%2,%3};"
        : "+f"(d0), "+f"(d1), "+f"(d2), "+f"(d3)
        : "r"(a0), "r"(a1), "r"(a2), "r"(a3), "r"(b0), "r"(b1));
}

// ---------------- LayerNorm + tri bias fused: one block (128 thr) per row --
__global__ void ln_tri_kernel(const float* __restrict__ x,
                              const float* __restrict__ w,
                              const float* __restrict__ b,
                              const float* __restrict__ w_tri) {
    int row = blockIdx.x;
    int t = threadIdx.x;
    float v = x[(size_t)row * CC + t];
    float s = v, sq = v * v;
    #pragma unroll
    for (int off = 16; off; off >>= 1) {
        s  += __shfl_xor_sync(0xffffffffu, s,  off);
        sq += __shfl_xor_sync(0xffffffffu, sq, off);
    }
    __shared__ float sh[8];
    __shared__ float sh2[4][4];
    int wid = t >> 5, lane = t & 31;
    if (lane == 0) { sh[wid] = s; sh[4 + wid] = sq; }
    __syncthreads();
    s  = sh[0] + sh[1] + sh[2] + sh[3];
    sq = sh[4] + sh[5] + sh[6] + sh[7];
    float mu  = s * (1.0f / CC);
    float var = sq * (1.0f / CC) - mu * mu;
    float rs  = rsqrtf(var + 1e-5f);
    float xn = (v - mu) * rs * w[t] + b[t];
    g_xn[(size_t)row * CC + t] = xn;

    // tri: dot(xn_row, w_tri[:,h]) for h=0..3
    float4 wt = ((const float4*)w_tri)[t];     // w_tri[t][0..3]
    float p0 = xn * wt.x, p1 = xn * wt.y, p2 = xn * wt.z, p3 = xn * wt.w;
    #pragma unroll
    for (int off = 16; off; off >>= 1) {
        p0 += __shfl_xor_sync(0xffffffffu, p0, off);
        p1 += __shfl_xor_sync(0xffffffffu, p1, off);
        p2 += __shfl_xor_sync(0xffffffffu, p2, off);
        p3 += __shfl_xor_sync(0xffffffffu, p3, off);
    }
    if (lane == 0) {
        sh2[wid][0] = p0; sh2[wid][1] = p1; sh2[wid][2] = p2; sh2[wid][3] = p3;
    }
    __syncthreads();
    if (t < 4) {
        float acc = sh2[0][t] + sh2[1][t] + sh2[2][t] + sh2[3][t];
        g_tri[(size_t)t * MROWS + row] = acc;
    }
}

// ---------------- tf32 GEMM: C[M,128] = alpha*A[M,128]@B[128,128] + bias ---
// 128x128 block tile, 256 threads = 8 warps (2 along M x 4 along N).
// Warp tile 64x32: 4 m16-tiles x 4 n8-tiles, mma m16n8k8 tf32.
// A staged in smem (tf32, stride 68 -> conflict-free frag loads).
// B fragments loaded straight from gmem (64KB matrix, L1/L2 resident).
#define AS_STR 68
__global__ void __launch_bounds__(256)
gemm_tf32(const float* __restrict__ A, const float* __restrict__ B,
          float* __restrict__ C, float alpha, const float* __restrict__ bias) {
    __shared__ unsigned As[128 * AS_STR];
    int tid  = threadIdx.x;
    int warp = tid >> 5, lane = tid & 31;
    int wm = warp >> 2, wn = warp & 3;       // wm 0..1, wn 0..3
    int m0 = blockIdx.x * 128;

    float4 acc[4][4];
    #pragma unroll
    for (int a = 0; a < 4; a++)
        #pragma unroll
        for (int b = 0; b < 4; b++) acc[a][b] = make_float4(0.f, 0.f, 0.f, 0.f);

    for (int kc = 0; kc < 128; kc += 64) {
        // stage A chunk 128x64 as tf32
        #pragma unroll
        for (int l = 0; l < 8; l++) {
            int idx = tid + l * 256;
            int mr = idx >> 4;
            int k4 = (idx & 15) * 4;
            float4 f = *(const float4*)(A + (size_t)(m0 + mr) * 128 + kc + k4);
            uint4 u;
            u.x = cvt_tf32(f.x); u.y = cvt_tf32(f.y);
            u.z = cvt_tf32(f.z); u.w = cvt_tf32(f.w);
            *(uint4*)(As + mr * AS_STR + k4) = u;
        }
        __syncthreads();

        #pragma unroll
        for (int ks = 0; ks < 8; ks++) {
            int kk = ks * 8;
            unsigned af[4][4];
            #pragma unroll
            for (int mi = 0; mi < 4; mi++) {
                int r = wm * 64 + mi * 16 + (lane >> 2);
                int c = kk + (lane & 3);
                af[mi][0] = As[r * AS_STR + c];
                af[mi][1] = As[(r + 8) * AS_STR + c];
                af[mi][2] = As[r * AS_STR + c + 4];
                af[mi][3] = As[(r + 8) * AS_STR + c + 4];
            }
            const float* Bp = B + (size_t)(kc + kk + (lane & 3)) * 128 + wn * 32 + (lane >> 2);
            #pragma unroll
            for (int ni = 0; ni < 4; ni++) {
                unsigned b0 = cvt_tf32(Bp[ni * 8]);
                unsigned b1 = cvt_tf32(Bp[4 * 128 + ni * 8]);
                #pragma unroll
                for (int mi = 0; mi < 4; mi++)
                    mma_tf32(acc[mi][ni].x, acc[mi][ni].y, acc[mi][ni].z, acc[mi][ni].w,
                             af[mi][0], af[mi][1], af[mi][2], af[mi][3], b0, b1);
            }
        }
        __syncthreads();
    }

    // store: c-frag mapping (row = lane/4 (+8), col = 2*(lane%3... lane&3))
    #pragma unroll
    for (int mi = 0; mi < 4; mi++) {
        int r = m0 + wm * 64 + mi * 16 + (lane >> 2);
        #pragma unroll
        for (int ni = 0; ni < 4; ni++) {
            int c = wn * 32 + ni * 8 + 2 * (lane & 3);
            float bx = bias ? bias[c] : 0.f;
            float by = bias ? bias[c + 1] : 0.f;
            float2 lo = make_float2(acc[mi][ni].x * alpha + bx, acc[mi][ni].y * alpha + by);
            float2 hi = make_float2(acc[mi][ni].z * alpha + bx, acc[mi][ni].w * alpha + by);
            *(float2*)(C + (size_t)r * 128 + c) = lo;
            *(float2*)(C + (size_t)(r + 8) * 128 + c) = hi;
        }
    }
}

// ---------------- attention: block per (qtile=64, h, i), 512 threads -----
// smem (floats): q[64][36] tf32, k[256][36] tf32, v[256][40] tf32,
//                s[64][260] fp32 scores (tf32 bits after softmax), mb[256]
#define QS_STR 36
#define KS_STR 36
#define VS_STR 40
#define SS_STR 260
#define SM_Q   0
#define SM_K   (SM_Q + 64 * QS_STR)
#define SM_V   (SM_K + 256 * KS_STR)
#define SM_S   (SM_V + 256 * VS_STR)
#define SM_MB  (SM_S + 64 * SS_STR)
#define ATTN_SMEM_FLOATS (SM_MB + 256)

__global__ void __launch_bounds__(512)
attn_kernel(const float* __restrict__ mask) {
    extern __shared__ float sm[];
    unsigned* q_su = (unsigned*)(sm + SM_Q);
    unsigned* k_su = (unsigned*)(sm + SM_K);
    unsigned* v_su = (unsigned*)(sm + SM_V);
    float*    s_s  = sm + SM_S;
    float*    mb_s = sm + SM_MB;

    int tid = threadIdx.x;
    int warp = tid >> 5, lane = tid & 31;
    int qt = blockIdx.x;       // 0..3
    int h  = blockIdx.y;       // 0..3
    int i  = blockIdx.z;       // 0..255

    if (tid < 256) mb_s[tid] = 1.0e9f * (mask[(size_t)i * BJ + tid] - 1.0f);

    // ---- fill q (64x32), k (256x32), v (256x32) as tf32 ----
    {
        int jr = tid >> 3, d4 = (tid & 7) * 4;
        int jg = qt * 64 + jr;
        float4 f = *(const float4*)(g_q + ((size_t)(i * BJ + jg) * HH + h) * CH + d4);
        uint4 u;
        u.x = cvt_tf32(f.x); u.y = cvt_tf32(f.y); u.z = cvt_tf32(f.z); u.w = cvt_tf32(f.w);
        *(uint4*)(q_su + jr * QS_STR + d4) = u;
    }
    #pragma unroll
    for (int l2 = 0; l2 < 4; l2++) {
        int idx = tid + l2 * 512;
        int jr = idx >> 3, d4 = (idx & 7) * 4;
        size_t base = ((size_t)(i * BJ + jr) * HH + h) * CH + d4;
        float4 fk = *(const float4*)(g_k + base);
        uint4 uk;
        uk.x = cvt_tf32(fk.x); uk.y = cvt_tf32(fk.y); uk.z = cvt_tf32(fk.z); uk.w = cvt_tf32(fk.w);
        *(uint4*)(k_su + jr * KS_STR + d4) = uk;
        float4 fv = *(const float4*)(g_v + base);
        uint4 uv;
        uv.x = cvt_tf32(fv.x); uv.y = cvt_tf32(fv.y); uv.z = cvt_tf32(fv.z); uv.w = cvt_tf32(fv.w);
        *(uint4*)(v_su + jr * VS_STR + d4) = uv;
    }
    __syncthreads();

    // ---- QK^T: M=64, N=256, K=32. 16 warps: 4(M) x 4(N), warp 16x64 ----
    {
        int m0w = (warp >> 2) * 16;
        int n0w = (warp & 3) * 64;
        float4 acc[8];
        #pragma unroll
        for (int nt = 0; nt < 8; nt++) acc[nt] = make_float4(0.f, 0.f, 0.f, 0.f);

        #pragma unroll
        for (int ks = 0; ks < 4; ks++) {
            int kk = ks * 8;
            int ar = m0w + (lane >> 2);
            int cA = kk + (lane & 3);
            unsigned a0 = q_su[ar * QS_STR + cA];
            unsigned a1 = q_su[(ar + 8) * QS_STR + cA];
            unsigned a2 = q_su[ar * QS_STR + cA + 4];
            unsigned a3 = q_su[(ar + 8) * QS_STR + cA + 4];
            #pragma unroll
            for (int nt = 0; nt < 8; nt++) {
                int n = n0w + nt * 8 + (lane >> 2);
                unsigned b0 = k_su[n * KS_STR + kk + (lane & 3)];
                unsigned b1 = k_su[n * KS_STR + kk + 4 + (lane & 3)];
                mma_tf32(acc[nt].x, acc[nt].y, acc[nt].z, acc[nt].w,
                         a0, a1, a2, a3, b0, b1);
            }
        }
        // epilogue: + tri bias + mask bias -> s_s
        int r0 = m0w + (lane >> 2);
        int qg = qt * 64 + r0;
        #pragma unroll
        for (int nt = 0; nt < 8; nt++) {
            int c = n0w + nt * 8 + 2 * (lane & 3);
            float2 t0  = *(const float2*)(g_tri + ((size_t)h * BI + qg) * BJ + c);
            float2 t1  = *(const float2*)(g_tri + ((size_t)h * BI + qg + 8) * BJ + c);
            float2 mbv = *(const float2*)(mb_s + c);
            s_s[r0 * SS_STR + c]           = acc[nt].x + t0.x + mbv.x;
            s_s[r0 * SS_STR + c + 1]       = acc[nt].y + t0.y + mbv.y;
            s_s[(r0 + 8) * SS_STR + c]     = acc[nt].z + t1.x + mbv.x;
            s_s[(r0 + 8) * SS_STR + c + 1] = acc[nt].w + t1.y + mbv.y;
        }
    }
    __syncthreads();

    // ---- softmax: warp-per-row, lane-strided scalar (conflict-free) ----
    {
        #pragma unroll
        for (int rr = 0; rr < 4; rr++) {
            int r = warp * 4 + rr;
            float* row = s_s + r * SS_STR;
            float e[8];
            float mx = -1e30f;
            #pragma unroll
            for (int t = 0; t < 8; t++) { e[t] = row[lane + 32 * t]; mx = fmaxf(mx, e[t]); }
            #pragma unroll
            for (int off = 16; off; off >>= 1)
                mx = fmaxf(mx, __shfl_xor_sync(0xffffffffu, mx, off));
            float sum = 0.f;
            #pragma unroll
            for (int t = 0; t < 8; t++) { e[t] = __expf(e[t] - mx); sum += e[t]; }
            #pragma unroll
            for (int off = 16; off; off >>= 1)
                sum += __shfl_xor_sync(0xffffffffu, sum, off);
            float inv = 1.0f / sum;
            unsigned* rowu = (unsigned*)row;
            #pragma unroll
            for (int t = 0; t < 8; t++) rowu[lane + 32 * t] = cvt_tf32(e[t] * inv);
        }
    }
    __syncthreads();

    // ---- AV: M=64, N=32, K=256. 16 warps: 4(M) x 4(N), warp 16x8 ----
    {
        int m0 = (warp >> 2) * 16;
        int n0 = (warp & 3) * 8;
        float4 acc = make_float4(0.f, 0.f, 0.f, 0.f);
        const unsigned* s_su = (const unsigned*)s_s;
        #pragma unroll 8
        for (int ks = 0; ks < 32; ks++) {
            int kk = ks * 8;
            int ar = m0 + (lane >> 2);
            int cA = kk + (lane & 3);
            unsigned a0 = s_su[ar * SS_STR + cA];
            unsigned a1 = s_su[(ar + 8) * SS_STR + cA];
            unsigned a2 = s_su[ar * SS_STR + cA + 4];
            unsigned a3 = s_su[(ar + 8) * SS_STR + cA + 4];
            int n = n0 + (lane >> 2);
            unsigned b0 = v_su[(kk + (lane & 3)) * VS_STR + n];
            unsigned b1 = v_su[(kk + 4 + (lane & 3)) * VS_STR + n];
            mma_tf32(acc.x, acc.y, acc.z, acc.w, a0, a1, a2, a3, b0, b1);
        }
        // gate (sigmoid) + store
        int qloc = m0 + (lane >> 2);
        int d = n0 + 2 * (lane & 3);
        #pragma unroll
        for (int half = 0; half < 2; half++) {
            int jq = qt * 64 + qloc + half * 8;
            size_t base = ((size_t)(i * BJ + jq) * HH + h) * CH + d;
            float2 gv = *(const float2*)(g_g + base);
            float vx = half ? acc.z : acc.x;
            float vy = half ? acc.w : acc.y;
            float2 ov;
            ov.x = vx / (1.0f + __expf(-gv.x));
            ov.y = vy / (1.0f + __expf(-gv.y));
            *(float2*)(g_o + base) = ov;
        }
    }
}

// ---------------- launch ----------------
extern "C" void kernel_launch(void* const* d_in, const int* in_sizes, int n_in,
                              void* d_out, int out_size) {
    const float* x     = (const float*)d_in[0];
    const float* mask  = (const float*)d_in[1];
    // d_in[2] = chunk_size (unused)
    const float* ln_w  = (const float*)d_in[3];
    const float* ln_b  = (const float*)d_in[4];
    const float* w_tri = (const float*)d_in[5];
    const float* wq    = (const float*)d_in[6];
    const float* wk    = (const float*)d_in[7];
    const float* wv    = (const float*)d_in[8];
    const float* wg    = (const float*)d_in[9];
    const float* bg    = (const float*)d_in[10];
    const float* wo    = (const float*)d_in[11];
    const float* bo    = (const float*)d_in[12];
    float* out = (float*)d_out;

    float *xn_p, *q_p, *k_p, *v_p, *g_p, *o_p;
    cudaGetSymbolAddress((void**)&xn_p, g_xn);
    cudaGetSymbolAddress((void**)&q_p,  g_q);
    cudaGetSymbolAddress((void**)&k_p,  g_k);
    cudaGetSymbolAddress((void**)&v_p,  g_v);
    cudaGetSymbolAddress((void**)&g_p,  g_g);
    cudaGetSymbolAddress((void**)&o_p,  g_o);

    ln_tri_kernel<<<MROWS, 128>>>(x, ln_w, ln_b, w_tri);

    const float qscale = 0.17677669529663687f;  // 32^-0.5
    gemm_tf32<<<MROWS / 128, 256>>>(xn_p, wq, q_p, qscale, nullptr);
    gemm_tf32<<<MROWS / 128, 256>>>(xn_p, wk, k_p, 1.0f, nullptr);
    gemm_tf32<<<MROWS / 128, 256>>>(xn_p, wv, v_p, 1.0f, nullptr);
    gemm_tf32<<<MROWS / 128, 256>>>(xn_p, wg, g_p, 1.0f, bg);

    cudaFuncSetAttribute(attn_kernel, cudaFuncAttributeMaxDynamicSharedMemorySize,
                         ATTN_SMEM_FLOATS * (int)sizeof(float));
    dim3 agrid(4, HH, BI);
    attn_kernel<<<agrid, 512, ATTN_SMEM_FLOATS * sizeof(float)>>>(mask);

    gemm_tf32<<<MROWS / 128, 256>>>(o_p, wo, out, 1.0f, bo);
}